// round 13
// baseline (speedup 1.0000x reference)
#include <cuda_runtime.h>
#include <cuda_bf16.h>
#include <math.h>
#include <cstdint>

// ---------------------------------------------------------------------------
// Problem constants
// ---------------------------------------------------------------------------
#define DIM     256
#define KCODES  2048
#define NROWS   65536
#define BM      128            // z rows per CTA
#define BN      128            // codes per tile
#define NTILES  16             // KCODES / BN
#define NSTEPS  32             // 16 tiles * 2 chunks (s8: 128 k-bytes/chunk)

#define QSCALE  24.0f          // int8 quant scale (clamp at ~5.3 sigma)
#define INV_S2  (1.0f / (QSCALE * QSCALE))
#define MARGIN  8.0f           // > pairwise int8-quant score error bound (~6)
#define QSLAB   8192           // global queue entries per CTA

#define A_CHUNK_BYTES 16384    // 128 rows * 128 s8
#define A_BYTES       32768    // 2 chunks cover k = 0..255
#define B_CHUNK_BYTES 16384
// smem layout (bytes):
//   [0, 32768)        A (2 chunks, s8)
//   [32768, 65536)    B double buffer (s8)
//   [65536, 66048)    rowminS[128] u32 (order-mapped float)
//   [66048, 67072)    rowbest[128] u64
//   [67072, 67076)    qcount
//   [67076, 67080)    qovf
#define OFF_ROWMIN  65536
#define OFF_ROWBEST 66048
#define OFF_QCOUNT  67072
#define OFF_QOVF    67076
#define SMEM_BYTES  67584

// ---------------------------------------------------------------------------
// Device scratch (static)
// ---------------------------------------------------------------------------
__device__ float g_enorm[KCODES];
__device__ int   g_index[NROWS];
__device__ float g_counts[KCODES];
__device__ float g_loss_sum;
__device__ __align__(16) uint8_t g_es[KCODES * DIM];            // 512 KB (s8)
__device__ uint32_t g_queue[(NROWS / BM) * QSLAB];              // 16 MB

// ---------------------------------------------------------------------------
// PTX helpers
// ---------------------------------------------------------------------------
__device__ __forceinline__ uint32_t smem_u32(const void* p) {
    uint32_t a;
    asm("{ .reg .u64 t; cvta.to.shared.u64 t, %1; cvt.u32.u64 %0, t; }"
        : "=r"(a) : "l"(p));
    return a;
}
__device__ __forceinline__ void cp16(uint32_t dst, const void* src) {
    asm volatile("cp.async.cg.shared.global [%0], [%1], 16;" :: "r"(dst), "l"(src));
}
#define CP_COMMIT() asm volatile("cp.async.commit_group;" ::: "memory")
#define CP_WAIT0()  asm volatile("cp.async.wait_group 0;" ::: "memory")

#define LDSM_X4(r, addr) \
    asm volatile("ldmatrix.sync.aligned.m8n8.x4.shared.b16 {%0,%1,%2,%3}, [%4];" \
        : "=r"((r)[0]), "=r"((r)[1]), "=r"((r)[2]), "=r"((r)[3]) : "r"(addr))

#define LDSM_X4B(r0, r1, r2, r3, addr) \
    asm volatile("ldmatrix.sync.aligned.m8n8.x4.shared.b16 {%0,%1,%2,%3}, [%4];" \
        : "=r"(r0), "=r"(r1), "=r"(r2), "=r"(r3) : "r"(addr))

// INT8 IMMA, k=32, s32 accumulate. Fragment maps = the k32 byte-wise maps
// proven correct in the R11 fp8 run (b16 view, 2 bytes per b16 along k).
#define MMA16832S8(d, a, b) \
    asm volatile("mma.sync.aligned.m16n8k32.row.col.s32.s8.s8.s32 " \
        "{%0,%1,%2,%3}, {%4,%5,%6,%7}, {%8,%9}, {%0,%1,%2,%3};" \
        : "+r"((d)[0]), "+r"((d)[1]), "+r"((d)[2]), "+r"((d)[3]) \
        : "r"((a)[0]), "r"((a)[1]), "r"((a)[2]), "r"((a)[3]), \
          "r"((b)[0]), "r"((b)[1]))

// Quantize 4 floats -> 4 packed s8 bytes (byte i = v_i).
__device__ __forceinline__ uint32_t pack4_s8(float v0, float v1, float v2, float v3) {
    int r0 = __float2int_rn(fminf(fmaxf(v0 * QSCALE, -127.f), 127.f));
    int r1 = __float2int_rn(fminf(fmaxf(v1 * QSCALE, -127.f), 127.f));
    int r2 = __float2int_rn(fminf(fmaxf(v2 * QSCALE, -127.f), 127.f));
    int r3 = __float2int_rn(fminf(fmaxf(v3 * QSCALE, -127.f), 127.f));
    return (uint32_t)(r0 & 0xFF) | ((uint32_t)(r1 & 0xFF) << 8) |
           ((uint32_t)(r2 & 0xFF) << 16) | ((uint32_t)(r3 & 0xFF) << 24);
}

// Order-preserving float <-> uint maps (atomicMin on u32).
__device__ __forceinline__ uint32_t fmap(float f) {
    uint32_t s = __float_as_uint(f);
    return (s & 0x80000000u) ? ~s : (s | 0x80000000u);
}
__device__ __forceinline__ float funmap(uint32_t u) {
    return (u & 0x80000000u) ? __uint_as_float(u & 0x7FFFFFFFu)
                             : __uint_as_float(~u);
}

// ---------------------------------------------------------------------------
// Prep: e -> g_es (s8) + fp32 half-norms + zero scratch. One warp per code.
// ---------------------------------------------------------------------------
__global__ void prep_e_kernel(const float* __restrict__ e) {
    int t = blockIdx.x * blockDim.x + threadIdx.x;
    int w = t >> 5, l = t & 31;
    if (w < KCODES) {
        const float4* row = (const float4*)(e + (size_t)w * DIM);
        float4 a = row[2 * l], b = row[2 * l + 1];
        uint2 p = make_uint2(pack4_s8(a.x, a.y, a.z, a.w),
                             pack4_s8(b.x, b.y, b.z, b.w));
        ((uint2*)g_es)[(size_t)w * 32 + l] = p;
        float s = a.x*a.x + a.y*a.y + a.z*a.z + a.w*a.w
                + b.x*b.x + b.y*b.y + b.z*b.z + b.w*b.w;
        #pragma unroll
        for (int o = 16; o; o >>= 1) s += __shfl_xor_sync(0xffffffffu, s, o);
        if (l == 0) { g_enorm[w] = 0.5f * s; g_counts[w] = 0.f; }
    }
    if (t == 0) g_loss_sum = 0.f;
}

// ---------------------------------------------------------------------------
// B tile fill: 128 codes x 128 s8 into swizzled smem. step = tile*2 + chunk.
// ---------------------------------------------------------------------------
__device__ __forceinline__ void fill_B(uint32_t sB, int step) {
    int tile = step >> 1, chunk = step & 1, buf = step & 1;
    const char* src0 = (const char*)g_es + (size_t)tile * BN * 256 + chunk * 128;
    uint32_t d0 = sB + buf * B_CHUNK_BYTES;
    #pragma unroll
    for (int o = 0; o < 8; ++o) {
        int idx = threadIdx.x + o * 128;
        int row = idx >> 3, seg = idx & 7;
        uint32_t dst = d0 + row * 128 + (((uint32_t)(seg ^ (row & 7))) << 4);
        cp16(dst, src0 + (size_t)row * 256 + seg * 16);
    }
}

// ---------------------------------------------------------------------------
// One s8 chunk: 4 k32-steps of (8 LDSM.x4 + 32 IMMA). Addressing identical
// to the proven k32 byte-wise maps (R11).
// ---------------------------------------------------------------------------
__device__ __forceinline__ void chunk_mma(
    uint32_t aBase, uint32_t bBase, int lane,
    int (&acc)[4][8][4], int wm, int wn)
{
    const int m = lane >> 3, r8 = lane & 7;
    #pragma unroll
    for (int ks = 0; ks < 4; ++ks) {
        uint32_t b[8][2];
        #pragma unroll
        for (int nb = 0; nb < 4; ++nb) {
            int code = wn + nb * 16 + ((m >> 1) << 3) + r8;
            int kseg = ks * 2 + (m & 1);
            uint32_t addr = bBase + code * 128 +
                            (((uint32_t)(kseg ^ (code & 7))) << 4);
            LDSM_X4B(b[2 * nb][0], b[2 * nb][1],
                     b[2 * nb + 1][0], b[2 * nb + 1][1], addr);
        }
        uint32_t a[4][4];
        #pragma unroll
        for (int mi = 0; mi < 4; ++mi) {
            int row = wm + mi * 16 + r8 + ((m & 1) << 3);
            int kseg = ks * 2 + (m >> 1);
            uint32_t addr = aBase + row * 128 +
                            (((uint32_t)(kseg ^ (row & 7))) << 4);
            LDSM_X4(a[mi], addr);
        }
        #pragma unroll
        for (int mi = 0; mi < 4; ++mi)
            #pragma unroll
            for (int ni = 0; ni < 8; ++ni)
                MMA16832S8(acc[mi][ni], a[mi], b[ni]);
    }
}

// ---------------------------------------------------------------------------
// Exact fp32 rescore; atomicMin packed (score|code) key. Post-loop only.
// ---------------------------------------------------------------------------
__device__ __forceinline__ void exact_rescore(
    const float* __restrict__ z, const float* __restrict__ e,
    int row0, int rloc, int code, unsigned long long* rowbest)
{
    const float4* zr = (const float4*)(z + (size_t)(row0 + rloc) * DIM);
    const float4* er = (const float4*)(e + (size_t)code * DIM);
    float a0 = 0.f, a1 = 0.f, a2 = 0.f, a3 = 0.f;
    #pragma unroll 8
    for (int i = 0; i < 64; ++i) {
        float4 zv = __ldg(&zr[i]);
        float4 ev = __ldg(&er[i]);
        a0 += zv.x * ev.x; a1 += zv.y * ev.y;
        a2 += zv.z * ev.z; a3 += zv.w * ev.w;
    }
    float sc = __ldg(&g_enorm[code]) - ((a0 + a1) + (a2 + a3));
    unsigned long long key = ((unsigned long long)fmap(sc) << 32) | (uint32_t)code;
    atomicMin(&rowbest[rloc], key);
}

// ---------------------------------------------------------------------------
// Main kernel: fused z->s8 quantize in prologue; single-pass s8 IMMA
// screening GEMM; merged stale-threshold epilogue (tile 0 seeds); mask-based
// enqueue; post-loop exact fp32 rescore; cold brute-force fallback on
// queue overflow.
// ---------------------------------------------------------------------------
__global__ void __launch_bounds__(128, 2)
argmin_mma_kernel(const float* __restrict__ z, const float* __restrict__ e,
                  float* __restrict__ out_idx) {
    extern __shared__ char smem[];
    const int tid = threadIdx.x, lane = tid & 31, w = tid >> 5;
    const int row0 = blockIdx.x * BM;
    const int wm = (w >> 1) * 64, wn = (w & 1) * 64;
    const uint32_t sA = smem_u32(smem);
    const uint32_t sB = sA + A_BYTES;
    uint32_t* rowminS = (uint32_t*)(smem + OFF_ROWMIN);
    unsigned long long* rowbest = (unsigned long long*)(smem + OFF_ROWBEST);
    int* qcount = (int*)(smem + OFF_QCOUNT);
    int* qovf   = (int*)(smem + OFF_QOVF);
    uint32_t* myq = g_queue + (size_t)blockIdx.x * QSLAB;

    rowbest[tid] = ~0ull;
    rowminS[tid] = fmap(3.0e38f);
    if (tid == 0) { *qcount = 0; *qovf = 0; }

    // ---- Prologue: B step 0 via cp.async; A = fused fp32->s8 quantize ----
    fill_B(sB, 0);
    CP_COMMIT();
    {
        // 4096 8-byte units cover the 128x256 A block (2 float4 -> u64).
        const float4* gz = (const float4*)(z + (size_t)row0 * DIM);
        #pragma unroll
        for (int o = 0; o < 32; ++o) {
            int u = tid + o * 128;            // u64 unit index
            int row = u >> 5, c8 = u & 31;
            float4 v0 = gz[(size_t)row * 64 + c8 * 2];
            float4 v1 = gz[(size_t)row * 64 + c8 * 2 + 1];
            uint32_t p0 = pack4_s8(v0.x, v0.y, v0.z, v0.w);
            uint32_t p1 = pack4_s8(v1.x, v1.y, v1.z, v1.w);
            int chunk = c8 >> 4;              // k half
            int seg = (c8 & 15) >> 1, half = c8 & 1;
            uint32_t dst = sA + chunk * A_CHUNK_BYTES + row * 128 +
                           (((uint32_t)(seg ^ (row & 7))) << 4) + half * 8;
            asm volatile("st.shared.v2.b32 [%0], {%1, %2};"
                         :: "r"(dst), "r"(p0), "r"(p1) : "memory");
        }
    }
    __syncthreads();   // A stores + shared init visible

    // ===================== Single GEMM pass with gating ====================
    int s = 0;
    for (int tile = 0; tile < NTILES; ++tile) {
        int acc[4][8][4];
        #pragma unroll
        for (int mi = 0; mi < 4; ++mi)
            #pragma unroll
            for (int ni = 0; ni < 8; ++ni)
                #pragma unroll
                for (int r = 0; r < 4; ++r) acc[mi][ni][r] = 0;
        for (int chunk = 0; chunk < 2; ++chunk, ++s) {
            CP_WAIT0();
            __syncthreads();
            if (s + 1 < NSTEPS) { fill_B(sB, s + 1); CP_COMMIT(); }
            chunk_mma(sA + chunk * A_CHUNK_BYTES,
                      sB + (s & 1) * B_CHUNK_BYTES, lane, acc, wm, wn);
        }

        // ---- Scores: sc = enorm - dot_q / QSCALE^2 (fp32) ----
        float scf[4][8][4];
        #pragma unroll
        for (int ni = 0; ni < 8; ++ni) {
            int c0 = tile * BN + wn + ni * 8 + ((lane & 3) << 1);
            float e0 = __ldg(&g_enorm[c0]);
            float e1 = __ldg(&g_enorm[c0 + 1]);
            #pragma unroll
            for (int mi = 0; mi < 4; ++mi) {
                scf[mi][ni][0] = e0 - (float)acc[mi][ni][0] * INV_S2;
                scf[mi][ni][1] = e1 - (float)acc[mi][ni][1] * INV_S2;
                scf[mi][ni][2] = e0 - (float)acc[mi][ni][2] * INV_S2;
                scf[mi][ni][3] = e1 - (float)acc[mi][ni][3] * INV_S2;
            }
        }

        // ---- Tile 0 only: seed threshold ----
        if (tile == 0) {
            #pragma unroll
            for (int mi = 0; mi < 4; ++mi) {
                #pragma unroll
                for (int h = 0; h < 2; ++h) {
                    float vmin = fminf(scf[mi][0][2*h], scf[mi][0][2*h+1]);
                    #pragma unroll
                    for (int ni = 1; ni < 8; ++ni)
                        vmin = fminf(vmin, fminf(scf[mi][ni][2*h], scf[mi][ni][2*h+1]));
                    int rloc = wm + mi * 16 + (lane >> 2) + h * 8;
                    atomicMin(&rowminS[rloc], fmap(vmin));
                }
            }
            __syncthreads();
        }

        // ---- Merged phase: stale threshold, mask gate, enqueue, min-update ----
        #pragma unroll
        for (int mi = 0; mi < 4; ++mi) {
            #pragma unroll
            for (int h = 0; h < 2; ++h) {
                int rloc = wm + mi * 16 + (lane >> 2) + h * 8;
                float thr = funmap(rowminS[rloc]) + MARGIN;
                float vmin = 3.0e38f;
                uint32_t mask = 0;
                #pragma unroll
                for (int ni = 0; ni < 8; ++ni) {
                    float v0 = scf[mi][ni][2*h], v1 = scf[mi][ni][2*h+1];
                    mask |= (v0 < thr) ? (1u << (2*ni))     : 0u;
                    mask |= (v1 < thr) ? (1u << (2*ni + 1)) : 0u;
                    vmin = fminf(vmin, fminf(v0, v1));
                }
                if (mask) {
                    int cb = tile * BN + wn + ((lane & 3) << 1);
                    do {
                        int b = __ffs(mask) - 1;
                        mask &= mask - 1;
                        int code = cb + (b >> 1) * 8 + (b & 1);
                        int qi = atomicAdd(qcount, 1);
                        if (qi < QSLAB) myq[qi] = ((uint32_t)rloc << 11) | (uint32_t)code;
                        else *qovf = 1;
                    } while (mask);
                }
                atomicMin(&rowminS[rloc], fmap(vmin));
            }
        }
    }

    // ======================= Exact fp32 rescore ============================
    __syncthreads();
    int qn = *qcount; if (qn > QSLAB) qn = QSLAB;
    for (int q = tid; q < qn; q += 128) {
        uint32_t ent = myq[q];
        exact_rescore(z, e, row0, (int)(ent >> 11), (int)(ent & 2047u), rowbest);
    }
    // Cold fallback: queue overflowed (never in practice) -> brute force.
    if (*qovf) {
        for (int code = 0; code < KCODES; ++code)
            exact_rescore(z, e, row0, tid, code, rowbest);
    }
    __syncthreads();

    // ---- Outputs: each thread owns one row ----
    {
        int bi = (int)(rowbest[tid] & 0xFFFFFFFFull);
        int row = row0 + tid;
        g_index[row] = bi;
        out_idx[row] = (float)bi;
        atomicAdd(&g_counts[bi], 1.0f);
    }
}

// ---------------------------------------------------------------------------
// Gather z_q + commitment-loss partials.
// ---------------------------------------------------------------------------
__global__ void gather_loss_kernel(const float* __restrict__ z,
                                   const float* __restrict__ e,
                                   float* __restrict__ out) {
    int i = blockIdx.x * blockDim.x + threadIdx.x;
    int row = i >> 6;
    int c4 = i & 63;
    int idx = g_index[row];
    float4 ev = ((const float4*)e)[(size_t)idx * 64 + c4];
    float4 zv = ((const float4*)z)[i];
    ((float4*)out)[i] = ev;
    float dx = ev.x - zv.x, dy = ev.y - zv.y;
    float dz = ev.z - zv.z, dw = ev.w - zv.w;
    float ls = dx * dx + dy * dy + dz * dz + dw * dw;

    __shared__ float red[32];
    #pragma unroll
    for (int o = 16; o; o >>= 1) ls += __shfl_xor_sync(0xffffffffu, ls, o);
    int l = threadIdx.x & 31, wq = threadIdx.x >> 5;
    if (l == 0) red[wq] = ls;
    __syncthreads();
    if (wq == 0) {
        float v = (l < ((int)blockDim.x >> 5)) ? red[l] : 0.f;
        #pragma unroll
        for (int o = 16; o; o >>= 1) v += __shfl_xor_sync(0xffffffffu, v, o);
        if (l == 0) atomicAdd(&g_loss_sum, v);
    }
}

// ---------------------------------------------------------------------------
// Finalize: loss scalar + perplexity.
// ---------------------------------------------------------------------------
__global__ void finalize_kernel(float* __restrict__ out) {
    const float invN = 1.0f / (float)NROWS;
    float s = 0.f;
    for (int k = threadIdx.x; k < KCODES; k += blockDim.x) {
        float p = g_counts[k] * invN;
        s += p * logf(p + 1e-10f);
    }
    __shared__ float red[32];
    #pragma unroll
    for (int o = 16; o; o >>= 1) s += __shfl_xor_sync(0xffffffffu, s, o);
    int l = threadIdx.x & 31, wq = threadIdx.x >> 5;
    if (l == 0) red[wq] = s;
    __syncthreads();
    if (wq == 0) {
        float v = (l < ((int)blockDim.x >> 5)) ? red[l] : 0.f;
        #pragma unroll
        for (int o = 16; o; o >>= 1) v += __shfl_xor_sync(0xffffffffu, v, o);
        if (l == 0) {
            const size_t NZ = (size_t)NROWS * DIM;
            out[NZ] = 0.25f * g_loss_sum / (float)NZ;
            out[NZ + 1 + NROWS] = expf(-v);
        }
    }
}

// ---------------------------------------------------------------------------
// Output layout (flattened tuple, float32):
//   [0, N*D) z_q_st | [N*D] loss | [N*D+1, +N) indices | [N*D+1+N] perplexity
// ---------------------------------------------------------------------------
extern "C" void kernel_launch(void* const* d_in, const int* in_sizes, int n_in,
                              void* d_out, int out_size) {
    const float* z = (const float*)d_in[0];
    const float* e = (const float*)d_in[1];
    float* out = (float*)d_out;

    cudaFuncSetAttribute(argmin_mma_kernel,
                         cudaFuncAttributeMaxDynamicSharedMemorySize, SMEM_BYTES);

    prep_e_kernel<<<KCODES * 32 / 256, 256>>>(e);
    argmin_mma_kernel<<<NROWS / BM, 128, SMEM_BYTES>>>(
        z, e, out + (size_t)NROWS * DIM + 1);
    gather_loss_kernel<<<(NROWS * (DIM / 4)) / 256, 256>>>(z, e, out);
    finalize_kernel<<<1, 256>>>(out);
}

// round 14
// speedup vs baseline: 1.9512x; 1.9512x over previous
#include <cuda_runtime.h>
#include <cuda_bf16.h>
#include <math.h>
#include <cstdint>

// ---------------------------------------------------------------------------
// Problem constants
// ---------------------------------------------------------------------------
#define DIM     256
#define KCODES  2048
#define NROWS   65536
#define BM      128            // z rows per CTA
#define BN      128            // codes per tile
#define NTILES  16             // KCODES / BN
#define NSTEPS  64             // 16 tiles * 4 chunks
#define NT      256            // 8 warps

#define MARGIN  1.5f           // > 2x max plausible hh-score error (~0.7)
#define QSLAB   8192           // global queue entries per CTA (exp ~500)

#define A_CHUNK_BYTES 16384    // 128 rows * 64 k * 2B
#define A_BYTES       65536    // 4 chunks (hh only)
#define B_CHUNK_BYTES 16384
// smem layout (bytes):
//   [0, 65536)         Ah (4 chunks)
//   [65536, 98304)     B double buffer
//   [98304, 98816)     rowminS[128] u32 (order-mapped float)
//   [98816, 99840)     rowbest[128] u64
//   [99840, 99844)     qcount
//   [99844, 99848)     qovf
#define OFF_ROWMIN  98304
#define OFF_ROWBEST 98816
#define OFF_QCOUNT  99840
#define OFF_QOVF    99844
#define SMEM_BYTES  100352

// ---------------------------------------------------------------------------
// Device scratch (static)
// ---------------------------------------------------------------------------
__device__ float g_enorm[KCODES];
__device__ int   g_index[NROWS];
__device__ float g_counts[KCODES];
__device__ float g_loss_sum;
__device__ __align__(16) __nv_bfloat16 g_es[KCODES * DIM];            // 1 MB (eh)
__device__ __align__(16) __nv_bfloat16 g_zs[(size_t)NROWS * DIM];     // 32 MB (zh)
__device__ uint32_t g_queue[(NROWS / BM) * QSLAB];                    // 16 MB

// ---------------------------------------------------------------------------
// PTX helpers
// ---------------------------------------------------------------------------
__device__ __forceinline__ uint32_t smem_u32(const void* p) {
    uint32_t a;
    asm("{ .reg .u64 t; cvta.to.shared.u64 t, %1; cvt.u32.u64 %0, t; }"
        : "=r"(a) : "l"(p));
    return a;
}
__device__ __forceinline__ void cp16(uint32_t dst, const void* src) {
    asm volatile("cp.async.cg.shared.global [%0], [%1], 16;" :: "r"(dst), "l"(src));
}
#define CP_COMMIT() asm volatile("cp.async.commit_group;" ::: "memory")
#define CP_WAIT0()  asm volatile("cp.async.wait_group 0;" ::: "memory")

#define LDSM_X4(r, addr) \
    asm volatile("ldmatrix.sync.aligned.m8n8.x4.shared.b16 {%0,%1,%2,%3}, [%4];" \
        : "=r"((r)[0]), "=r"((r)[1]), "=r"((r)[2]), "=r"((r)[3]) : "r"(addr))

#define LDSM_X4B(r0, r1, r2, r3, addr) \
    asm volatile("ldmatrix.sync.aligned.m8n8.x4.shared.b16 {%0,%1,%2,%3}, [%4];" \
        : "=r"(r0), "=r"(r1), "=r"(r2), "=r"(r3) : "r"(addr))

#define MMA16816(d, a, b) \
    asm volatile("mma.sync.aligned.m16n8k16.row.col.f32.bf16.bf16.f32 " \
        "{%0,%1,%2,%3}, {%4,%5,%6,%7}, {%8,%9}, {%0,%1,%2,%3};" \
        : "+f"((d)[0]), "+f"((d)[1]), "+f"((d)[2]), "+f"((d)[3]) \
        : "r"((a)[0]), "r"((a)[1]), "r"((a)[2]), "r"((a)[3]), \
          "r"((b)[0]), "r"((b)[1]))

__device__ __forceinline__ uint32_t pack2h(float a, float b) {
    __nv_bfloat16 h0 = __float2bfloat16(a), h1 = __float2bfloat16(b);
    return ((uint32_t)__bfloat16_as_ushort(h1) << 16) |
           (uint32_t)__bfloat16_as_ushort(h0);
}

// Order-preserving float <-> uint maps (atomicMin on u32).
__device__ __forceinline__ uint32_t fmap(float f) {
    uint32_t s = __float_as_uint(f);
    return (s & 0x80000000u) ? ~s : (s | 0x80000000u);
}
__device__ __forceinline__ float funmap(uint32_t u) {
    return (u & 0x80000000u) ? __uint_as_float(u & 0x7FFFFFFFu)
                             : __uint_as_float(~u);
}

// ---------------------------------------------------------------------------
// Prep 1: z -> g_zs (bf16 hi). One thread per float4.
// ---------------------------------------------------------------------------
__global__ void prep_z_kernel(const float* __restrict__ z) {
    int i = blockIdx.x * blockDim.x + threadIdx.x;
    float4 v = ((const float4*)z)[i];
    ((uint2*)g_zs)[i] = make_uint2(pack2h(v.x, v.y), pack2h(v.z, v.w));
}

// ---------------------------------------------------------------------------
// Prep 2: e -> g_es (bf16 hi) + half-norms + zero scratch. One warp per code.
// ---------------------------------------------------------------------------
__global__ void prep_e_kernel(const float* __restrict__ e) {
    int t = blockIdx.x * blockDim.x + threadIdx.x;
    int w = t >> 5, l = t & 31;
    if (w < KCODES) {
        const float4* row = (const float4*)(e + (size_t)w * DIM);
        float4 a = row[2 * l], b = row[2 * l + 1];
        uint32_t ph[4] = {pack2h(a.x, a.y), pack2h(a.z, a.w),
                          pack2h(b.x, b.y), pack2h(b.z, b.w)};
        ((uint4*)g_es)[(size_t)w * 32 + l] = *(uint4*)ph;
        float s = a.x*a.x + a.y*a.y + a.z*a.z + a.w*a.w
                + b.x*b.x + b.y*b.y + b.z*b.z + b.w*b.w;
        #pragma unroll
        for (int o = 16; o; o >>= 1) s += __shfl_xor_sync(0xffffffffu, s, o);
        if (l == 0) { g_enorm[w] = 0.5f * s; g_counts[w] = 0.f; }
    }
    if (t == 0) g_loss_sum = 0.f;
}

// ---------------------------------------------------------------------------
// B tile fill: 128 codes x 64 k of eh into swizzled smem. step: tile*4+chunk.
// 256 threads -> 4 units each.
// ---------------------------------------------------------------------------
__device__ __forceinline__ void fill_B(uint32_t sB, int step) {
    int tile = step >> 2, chunk = step & 3, buf = step & 1;
    const char* src0 = (const char*)g_es + (size_t)tile * BN * 512 + chunk * 128;
    uint32_t d0 = sB + buf * B_CHUNK_BYTES;
    #pragma unroll
    for (int o = 0; o < 4; ++o) {
        int idx = threadIdx.x + o * NT;
        int row = idx >> 3, seg = idx & 7;
        uint32_t dst = d0 + row * 128 + (((uint32_t)(seg ^ (row & 7))) << 4);
        cp16(dst, src0 + (size_t)row * 512 + seg * 16);
    }
}

// ---------------------------------------------------------------------------
// One hh chunk, 8-warp version: warp tile 64x32.
// Per ks: 2 B LDSM.x4 + 4 A LDSM.x4 + 16 MMA. Lane maps identical to R10.
// ---------------------------------------------------------------------------
__device__ __forceinline__ void chunk_mma(
    uint32_t aBase, uint32_t bBase, int lane,
    float (&acc)[4][4][4], int wm, int wn)
{
    const int m = lane >> 3, r8 = lane & 7;
    #pragma unroll
    for (int ks = 0; ks < 4; ++ks) {
        uint32_t b[4][2];
        #pragma unroll
        for (int nb = 0; nb < 2; ++nb) {
            int code = wn + nb * 16 + ((m >> 1) << 3) + r8;
            int kseg = ks * 2 + (m & 1);
            uint32_t addr = bBase + code * 128 +
                            (((uint32_t)(kseg ^ (code & 7))) << 4);
            LDSM_X4B(b[2 * nb][0], b[2 * nb][1],
                     b[2 * nb + 1][0], b[2 * nb + 1][1], addr);
        }
        uint32_t a[4][4];
        #pragma unroll
        for (int mi = 0; mi < 4; ++mi) {
            int row = wm + mi * 16 + r8 + ((m & 1) << 3);
            int kseg = ks * 2 + (m >> 1);
            uint32_t addr = aBase + row * 128 +
                            (((uint32_t)(kseg ^ (row & 7))) << 4);
            LDSM_X4(a[mi], addr);
        }
        #pragma unroll
        for (int mi = 0; mi < 4; ++mi)
            #pragma unroll
            for (int ni = 0; ni < 4; ++ni)
                MMA16816(acc[mi][ni], a[mi], b[ni]);
    }
}

// ---------------------------------------------------------------------------
// Exact fp32 rescore; atomicMin packed (score|code) key. Post-loop only.
// ---------------------------------------------------------------------------
__device__ __forceinline__ void exact_rescore(
    const float* __restrict__ z, const float* __restrict__ e,
    int row0, int rloc, int code, unsigned long long* rowbest)
{
    const float4* zr = (const float4*)(z + (size_t)(row0 + rloc) * DIM);
    const float4* er = (const float4*)(e + (size_t)code * DIM);
    float a0 = 0.f, a1 = 0.f, a2 = 0.f, a3 = 0.f;
    #pragma unroll 8
    for (int i = 0; i < 64; ++i) {
        float4 zv = __ldg(&zr[i]);
        float4 ev = __ldg(&er[i]);
        a0 += zv.x * ev.x; a1 += zv.y * ev.y;
        a2 += zv.z * ev.z; a3 += zv.w * ev.w;
    }
    float sc = __ldg(&g_enorm[code]) - ((a0 + a1) + (a2 + a3));
    unsigned long long key = ((unsigned long long)fmap(sc) << 32) | (uint32_t)code;
    atomicMin(&rowbest[rloc], key);
}

// ---------------------------------------------------------------------------
// Main kernel (8 warps, warp tile 64x32): single-pass hh GEMM; per-tile
// two-phase epilogue (reg min -> shared rowmin; constant-threshold mask
// gating to global queue); post-loop exact fp32 rescore; cold fallback.
// ---------------------------------------------------------------------------
__global__ void __launch_bounds__(NT, 2)
argmin_mma_kernel(const float* __restrict__ z, const float* __restrict__ e,
                  float* __restrict__ out_idx) {
    extern __shared__ char smem[];
    const int tid = threadIdx.x, lane = tid & 31, w = tid >> 5;
    const int row0 = blockIdx.x * BM;
    const int wm = (w >> 2) * 64, wn = (w & 3) * 32;
    const uint32_t sA = smem_u32(smem);
    const uint32_t sB = sA + A_BYTES;
    uint32_t* rowminS = (uint32_t*)(smem + OFF_ROWMIN);
    unsigned long long* rowbest = (unsigned long long*)(smem + OFF_ROWBEST);
    int* qcount = (int*)(smem + OFF_QCOUNT);
    int* qovf   = (int*)(smem + OFF_QOVF);
    uint32_t* myq = g_queue + (size_t)blockIdx.x * QSLAB;

    if (tid < BM) { rowbest[tid] = ~0ull; rowminS[tid] = fmap(3.0e38f); }
    if (tid == 0) { *qcount = 0; *qovf = 0; }

    // ---- Prologue: Ah (4 chunks) + B step 0 ----
    {
        const char* gA = (const char*)g_zs + (size_t)row0 * 512;
        for (int o = tid; o < 4096; o += NT) {
            int chunk = o >> 10, rem = o & 1023;
            int row = rem >> 3, seg = rem & 7;
            uint32_t dst = sA + chunk * A_CHUNK_BYTES + row * 128 +
                           (((uint32_t)(seg ^ (row & 7))) << 4);
            cp16(dst, gA + (size_t)row * 512 + chunk * 128 + seg * 16);
        }
        fill_B(sB, 0);
        CP_COMMIT();
    }
    __syncthreads();   // shared init visible

    // ===================== Single GEMM pass with gating ====================
    int s = 0;
    for (int tile = 0; tile < NTILES; ++tile) {
        float acc[4][4][4];
        #pragma unroll
        for (int mi = 0; mi < 4; ++mi)
            #pragma unroll
            for (int ni = 0; ni < 4; ++ni)
                #pragma unroll
                for (int r = 0; r < 4; ++r) acc[mi][ni][r] = 0.f;
        for (int chunk = 0; chunk < 4; ++chunk, ++s) {
            CP_WAIT0();
            __syncthreads();
            if (s + 1 < NSTEPS) { fill_B(sB, s + 1); CP_COMMIT(); }
            chunk_mma(sA + chunk * A_CHUNK_BYTES,
                      sB + (s & 1) * B_CHUNK_BYTES, lane, acc, wm, wn);
        }

        // ---- Phase 1: scores in place, register min, shared atomicMin ----
        #pragma unroll
        for (int ni = 0; ni < 4; ++ni) {
            int c0 = tile * BN + wn + ni * 8 + ((lane & 3) << 1);
            float e0 = __ldg(&g_enorm[c0]);
            float e1 = __ldg(&g_enorm[c0 + 1]);
            #pragma unroll
            for (int mi = 0; mi < 4; ++mi) {
                acc[mi][ni][0] = e0 - acc[mi][ni][0];
                acc[mi][ni][1] = e1 - acc[mi][ni][1];
                acc[mi][ni][2] = e0 - acc[mi][ni][2];
                acc[mi][ni][3] = e1 - acc[mi][ni][3];
            }
        }
        #pragma unroll
        for (int mi = 0; mi < 4; ++mi) {
            #pragma unroll
            for (int h = 0; h < 2; ++h) {
                float vmin = fminf(acc[mi][0][2*h], acc[mi][0][2*h+1]);
                #pragma unroll
                for (int ni = 1; ni < 4; ++ni)
                    vmin = fminf(vmin, fminf(acc[mi][ni][2*h], acc[mi][ni][2*h+1]));
                int rloc = wm + mi * 16 + (lane >> 2) + h * 8;
                atomicMin(&rowminS[rloc], fmap(vmin));
            }
        }
        __syncthreads();

        // ---- Phase 2: branch-free masks; one cold branch per slice ----
        #pragma unroll
        for (int mi = 0; mi < 4; ++mi) {
            #pragma unroll
            for (int h = 0; h < 2; ++h) {
                int rloc = wm + mi * 16 + (lane >> 2) + h * 8;
                float thr = funmap(rowminS[rloc]) + MARGIN;
                uint32_t mask = 0;
                #pragma unroll
                for (int ni = 0; ni < 4; ++ni) {
                    mask |= (acc[mi][ni][2*h]   < thr) ? (1u << (2*ni))     : 0u;
                    mask |= (acc[mi][ni][2*h+1] < thr) ? (1u << (2*ni + 1)) : 0u;
                }
                if (mask) {
                    int cb = tile * BN + wn + ((lane & 3) << 1);
                    do {
                        int b = __ffs(mask) - 1;
                        mask &= mask - 1;
                        int code = cb + (b >> 1) * 8 + (b & 1);
                        int qi = atomicAdd(qcount, 1);
                        if (qi < QSLAB) myq[qi] = ((uint32_t)rloc << 11) | (uint32_t)code;
                        else *qovf = 1;
                    } while (mask);
                }
            }
        }
    }

    // ======================= Exact fp32 rescore ============================
    __syncthreads();
    int qn = *qcount; if (qn > QSLAB) qn = QSLAB;
    for (int q = tid; q < qn; q += NT) {
        uint32_t ent = myq[q];
        exact_rescore(z, e, row0, (int)(ent >> 11), (int)(ent & 2047u), rowbest);
    }
    // Cold fallback: queue overflowed (never in practice) -> brute force.
    if (*qovf) {
        for (int code = (tid >> 7); code < KCODES; code += 2)
            exact_rescore(z, e, row0, tid & 127, code, rowbest);
    }
    __syncthreads();

    // ---- Outputs: threads 0..127 own one row each ----
    if (tid < BM) {
        int bi = (int)(rowbest[tid] & 0xFFFFFFFFull);
        int row = row0 + tid;
        g_index[row] = bi;
        out_idx[row] = (float)bi;
        atomicAdd(&g_counts[bi], 1.0f);
    }
}

// ---------------------------------------------------------------------------
// Gather z_q + commitment-loss partials.
// ---------------------------------------------------------------------------
__global__ void gather_loss_kernel(const float* __restrict__ z,
                                   const float* __restrict__ e,
                                   float* __restrict__ out) {
    int i = blockIdx.x * blockDim.x + threadIdx.x;
    int row = i >> 6;
    int c4 = i & 63;
    int idx = g_index[row];
    float4 ev = ((const float4*)e)[(size_t)idx * 64 + c4];
    float4 zv = ((const float4*)z)[i];
    ((float4*)out)[i] = ev;
    float dx = ev.x - zv.x, dy = ev.y - zv.y;
    float dz = ev.z - zv.z, dw = ev.w - zv.w;
    float ls = dx * dx + dy * dy + dz * dz + dw * dw;

    __shared__ float red[32];
    #pragma unroll
    for (int o = 16; o; o >>= 1) ls += __shfl_xor_sync(0xffffffffu, ls, o);
    int l = threadIdx.x & 31, wq = threadIdx.x >> 5;
    if (l == 0) red[wq] = ls;
    __syncthreads();
    if (wq == 0) {
        float v = (l < ((int)blockDim.x >> 5)) ? red[l] : 0.f;
        #pragma unroll
        for (int o = 16; o; o >>= 1) v += __shfl_xor_sync(0xffffffffu, v, o);
        if (l == 0) atomicAdd(&g_loss_sum, v);
    }
}

// ---------------------------------------------------------------------------
// Finalize: loss scalar + perplexity.
// ---------------------------------------------------------------------------
__global__ void finalize_kernel(float* __restrict__ out) {
    const float invN = 1.0f / (float)NROWS;
    float s = 0.f;
    for (int k = threadIdx.x; k < KCODES; k += blockDim.x) {
        float p = g_counts[k] * invN;
        s += p * logf(p + 1e-10f);
    }
    __shared__ float red[32];
    #pragma unroll
    for (int o = 16; o; o >>= 1) s += __shfl_xor_sync(0xffffffffu, s, o);
    int l = threadIdx.x & 31, wq = threadIdx.x >> 5;
    if (l == 0) red[wq] = s;
    __syncthreads();
    if (wq == 0) {
        float v = (l < ((int)blockDim.x >> 5)) ? red[l] : 0.f;
        #pragma unroll
        for (int o = 16; o; o >>= 1) v += __shfl_xor_sync(0xffffffffu, v, o);
        if (l == 0) {
            const size_t NZ = (size_t)NROWS * DIM;
            out[NZ] = 0.25f * g_loss_sum / (float)NZ;
            out[NZ + 1 + NROWS] = expf(-v);
        }
    }
}

// ---------------------------------------------------------------------------
// Output layout (flattened tuple, float32):
//   [0, N*D) z_q_st | [N*D] loss | [N*D+1, +N) indices | [N*D+1+N] perplexity
// ---------------------------------------------------------------------------
extern "C" void kernel_launch(void* const* d_in, const int* in_sizes, int n_in,
                              void* d_out, int out_size) {
    const float* z = (const float*)d_in[0];
    const float* e = (const float*)d_in[1];
    float* out = (float*)d_out;

    cudaFuncSetAttribute(argmin_mma_kernel,
                         cudaFuncAttributeMaxDynamicSharedMemorySize, SMEM_BYTES);

    prep_z_kernel<<<(NROWS * 64) / 256, 256>>>(z);
    prep_e_kernel<<<KCODES * 32 / 256, 256>>>(e);
    argmin_mma_kernel<<<NROWS / BM, NT, SMEM_BYTES>>>(
        z, e, out + (size_t)NROWS * DIM + 1);
    gather_loss_kernel<<<(NROWS * (DIM / 4)) / 256, 256>>>(z, e, out);
    finalize_kernel<<<1, 256>>>(out);
}

// round 15
// speedup vs baseline: 1.9735x; 1.0114x over previous
#include <cuda_runtime.h>
#include <cuda_bf16.h>
#include <math.h>
#include <cstdint>

// ---------------------------------------------------------------------------
// Problem constants
// ---------------------------------------------------------------------------
#define DIM     256
#define KCODES  2048
#define NROWS   65536
#define BM      128            // z rows per CTA
#define BN      128            // codes per tile
#define NTILES  16             // KCODES / BN
#define NSTEPS  64             // 16 tiles * 4 chunks

#define MARGIN  1.5f           // > 2x max plausible hh-score error (~0.7)
#define QSLAB   8192           // global queue entries per CTA (exp ~500)

#define A_CHUNK_BYTES 16384    // 128 rows * 64 k * 2B
#define A_BYTES       65536    // 4 chunks (hh only)
#define B_CHUNK_BYTES 16384
// smem layout (bytes):
//   [0, 65536)         Ah (4 chunks)
//   [65536, 98304)     B double buffer
//   [98304, 98816)     rowminS[128] u32 (order-mapped float; reused as idx)
//   [98816, 99840)     rowbest[128] u64
//   [99840, 99844)     qcount
//   [99844, 99848)     qovf
#define OFF_ROWMIN  98304
#define OFF_ROWBEST 98816
#define OFF_QCOUNT  99840
#define OFF_QOVF    99844
#define SMEM_BYTES  100352

// ---------------------------------------------------------------------------
// Device scratch (static)
// ---------------------------------------------------------------------------
__device__ float g_enorm[KCODES];
__device__ float g_counts[KCODES];
__device__ float g_loss_sum;
__device__ __align__(16) __nv_bfloat16 g_es[KCODES * DIM];            // 1 MB (eh)
__device__ __align__(16) __nv_bfloat16 g_zs[(size_t)NROWS * DIM];     // 32 MB (zh)
__device__ uint32_t g_queue[(NROWS / BM) * QSLAB];                    // 16 MB

// ---------------------------------------------------------------------------
// PTX helpers
// ---------------------------------------------------------------------------
__device__ __forceinline__ uint32_t smem_u32(const void* p) {
    uint32_t a;
    asm("{ .reg .u64 t; cvta.to.shared.u64 t, %1; cvt.u32.u64 %0, t; }"
        : "=r"(a) : "l"(p));
    return a;
}
__device__ __forceinline__ void cp16(uint32_t dst, const void* src) {
    asm volatile("cp.async.cg.shared.global [%0], [%1], 16;" :: "r"(dst), "l"(src));
}
#define CP_COMMIT() asm volatile("cp.async.commit_group;" ::: "memory")
#define CP_WAIT0()  asm volatile("cp.async.wait_group 0;" ::: "memory")

#define LDSM_X4(r, addr) \
    asm volatile("ldmatrix.sync.aligned.m8n8.x4.shared.b16 {%0,%1,%2,%3}, [%4];" \
        : "=r"((r)[0]), "=r"((r)[1]), "=r"((r)[2]), "=r"((r)[3]) : "r"(addr))

#define LDSM_X4B(r0, r1, r2, r3, addr) \
    asm volatile("ldmatrix.sync.aligned.m8n8.x4.shared.b16 {%0,%1,%2,%3}, [%4];" \
        : "=r"(r0), "=r"(r1), "=r"(r2), "=r"(r3) : "r"(addr))

#define MMA16816(d, a, b) \
    asm volatile("mma.sync.aligned.m16n8k16.row.col.f32.bf16.bf16.f32 " \
        "{%0,%1,%2,%3}, {%4,%5,%6,%7}, {%8,%9}, {%0,%1,%2,%3};" \
        : "+f"((d)[0]), "+f"((d)[1]), "+f"((d)[2]), "+f"((d)[3]) \
        : "r"((a)[0]), "r"((a)[1]), "r"((a)[2]), "r"((a)[3]), \
          "r"((b)[0]), "r"((b)[1]))

__device__ __forceinline__ uint32_t pack2h(float a, float b) {
    __nv_bfloat16 h0 = __float2bfloat16(a), h1 = __float2bfloat16(b);
    return ((uint32_t)__bfloat16_as_ushort(h1) << 16) |
           (uint32_t)__bfloat16_as_ushort(h0);
}

// Order-preserving float <-> uint maps (atomicMin on u32).
__device__ __forceinline__ uint32_t fmap(float f) {
    uint32_t s = __float_as_uint(f);
    return (s & 0x80000000u) ? ~s : (s | 0x80000000u);
}
__device__ __forceinline__ float funmap(uint32_t u) {
    return (u & 0x80000000u) ? __uint_as_float(u & 0x7FFFFFFFu)
                             : __uint_as_float(~u);
}

// ---------------------------------------------------------------------------
// Prep 1: z -> g_zs (bf16 hi). One thread per float4.
// ---------------------------------------------------------------------------
__global__ void prep_z_kernel(const float* __restrict__ z) {
    int i = blockIdx.x * blockDim.x + threadIdx.x;
    float4 v = ((const float4*)z)[i];
    ((uint2*)g_zs)[i] = make_uint2(pack2h(v.x, v.y), pack2h(v.z, v.w));
}

// ---------------------------------------------------------------------------
// Prep 2: e -> g_es (bf16 hi) + half-norms + zero scratch. One warp per code.
// ---------------------------------------------------------------------------
__global__ void prep_e_kernel(const float* __restrict__ e) {
    int t = blockIdx.x * blockDim.x + threadIdx.x;
    int w = t >> 5, l = t & 31;
    if (w < KCODES) {
        const float4* row = (const float4*)(e + (size_t)w * DIM);
        float4 a = row[2 * l], b = row[2 * l + 1];
        uint32_t ph[4] = {pack2h(a.x, a.y), pack2h(a.z, a.w),
                          pack2h(b.x, b.y), pack2h(b.z, b.w)};
        ((uint4*)g_es)[(size_t)w * 32 + l] = *(uint4*)ph;
        float s = a.x*a.x + a.y*a.y + a.z*a.z + a.w*a.w
                + b.x*b.x + b.y*b.y + b.z*b.z + b.w*b.w;
        #pragma unroll
        for (int o = 16; o; o >>= 1) s += __shfl_xor_sync(0xffffffffu, s, o);
        if (l == 0) { g_enorm[w] = 0.5f * s; g_counts[w] = 0.f; }
    }
    if (t == 0) g_loss_sum = 0.f;
}

// ---------------------------------------------------------------------------
// B tile fill: 128 codes x 64 k of eh into swizzled smem. step: tile*4+chunk.
// ---------------------------------------------------------------------------
__device__ __forceinline__ void fill_B(uint32_t sB, int step) {
    int tile = step >> 2, chunk = step & 3, buf = step & 1;
    const char* src0 = (const char*)g_es + (size_t)tile * BN * 512 + chunk * 128;
    uint32_t d0 = sB + buf * B_CHUNK_BYTES;
    #pragma unroll
    for (int o = 0; o < 8; ++o) {
        int idx = threadIdx.x + o * 128;
        int row = idx >> 3, seg = idx & 7;
        uint32_t dst = d0 + row * 128 + (((uint32_t)(seg ^ (row & 7))) << 4);
        cp16(dst, src0 + (size_t)row * 512 + seg * 16);
    }
}

// ---------------------------------------------------------------------------
// One hh chunk: 4 ks-steps of (8 LDSM.x4 + 32 MMA). Maps proven R5/R6/R10.
// ---------------------------------------------------------------------------
__device__ __forceinline__ void chunk_mma(
    uint32_t aBase, uint32_t bBase, int lane,
    float (&acc)[4][8][4], int wm, int wn)
{
    const int m = lane >> 3, r8 = lane & 7;
    #pragma unroll
    for (int ks = 0; ks < 4; ++ks) {
        uint32_t b[8][2];
        #pragma unroll
        for (int nb = 0; nb < 4; ++nb) {
            int code = wn + nb * 16 + ((m >> 1) << 3) + r8;
            int kseg = ks * 2 + (m & 1);
            uint32_t addr = bBase + code * 128 +
                            (((uint32_t)(kseg ^ (code & 7))) << 4);
            LDSM_X4B(b[2 * nb][0], b[2 * nb][1],
                     b[2 * nb + 1][0], b[2 * nb + 1][1], addr);
        }
        uint32_t a[4][4];
        #pragma unroll
        for (int mi = 0; mi < 4; ++mi) {
            int row = wm + mi * 16 + r8 + ((m & 1) << 3);
            int kseg = ks * 2 + (m >> 1);
            uint32_t addr = aBase + row * 128 +
                            (((uint32_t)(kseg ^ (row & 7))) << 4);
            LDSM_X4(a[mi], addr);
        }
        #pragma unroll
        for (int mi = 0; mi < 4; ++mi)
            #pragma unroll
            for (int ni = 0; ni < 8; ++ni)
                MMA16816(acc[mi][ni], a[mi], b[ni]);
    }
}

// ---------------------------------------------------------------------------
// Exact fp32 rescore; atomicMin packed (score|code) key. Post-loop only.
// ---------------------------------------------------------------------------
__device__ __forceinline__ void exact_rescore(
    const float* __restrict__ z, const float* __restrict__ e,
    int row0, int rloc, int code, unsigned long long* rowbest)
{
    const float4* zr = (const float4*)(z + (size_t)(row0 + rloc) * DIM);
    const float4* er = (const float4*)(e + (size_t)code * DIM);
    float a0 = 0.f, a1 = 0.f, a2 = 0.f, a3 = 0.f;
    #pragma unroll 8
    for (int i = 0; i < 64; ++i) {
        float4 zv = __ldg(&zr[i]);
        float4 ev = __ldg(&er[i]);
        a0 += zv.x * ev.x; a1 += zv.y * ev.y;
        a2 += zv.z * ev.z; a3 += zv.w * ev.w;
    }
    float sc = __ldg(&g_enorm[code]) - ((a0 + a1) + (a2 + a3));
    unsigned long long key = ((unsigned long long)fmap(sc) << 32) | (uint32_t)code;
    atomicMin(&rowbest[rloc], key);
}

// ---------------------------------------------------------------------------
// Main kernel: single-pass hh GEMM (R10 structure) + fused tail that does
// the z_q gather, commitment-loss partial, index output, and histogram.
// ---------------------------------------------------------------------------
__global__ void __launch_bounds__(128, 2)
argmin_mma_kernel(const float* __restrict__ z, const float* __restrict__ e,
                  float* __restrict__ out) {
    extern __shared__ char smem[];
    const int tid = threadIdx.x, lane = tid & 31, w = tid >> 5;
    const int row0 = blockIdx.x * BM;
    const int wm = (w >> 1) * 64, wn = (w & 1) * 64;
    const uint32_t sA = smem_u32(smem);
    const uint32_t sB = sA + A_BYTES;
    uint32_t* rowminS = (uint32_t*)(smem + OFF_ROWMIN);
    unsigned long long* rowbest = (unsigned long long*)(smem + OFF_ROWBEST);
    int* qcount = (int*)(smem + OFF_QCOUNT);
    int* qovf   = (int*)(smem + OFF_QOVF);
    uint32_t* myq = g_queue + (size_t)blockIdx.x * QSLAB;

    rowbest[tid] = ~0ull;
    rowminS[tid] = fmap(3.0e38f);
    if (tid == 0) { *qcount = 0; *qovf = 0; }

    // ---- Prologue: Ah (4 chunks) + B step 0 ----
    {
        const char* gA = (const char*)g_zs + (size_t)row0 * 512;
        for (int o = tid; o < 4096; o += 128) {
            int chunk = o >> 10, rem = o & 1023;
            int row = rem >> 3, seg = rem & 7;
            uint32_t dst = sA + chunk * A_CHUNK_BYTES + row * 128 +
                           (((uint32_t)(seg ^ (row & 7))) << 4);
            cp16(dst, gA + (size_t)row * 512 + chunk * 128 + seg * 16);
        }
        fill_B(sB, 0);
        CP_COMMIT();
    }
    __syncthreads();   // shared init visible

    // ===================== Single GEMM pass with gating ====================
    int s = 0;
    for (int tile = 0; tile < NTILES; ++tile) {
        float acc[4][8][4];
        #pragma unroll
        for (int mi = 0; mi < 4; ++mi)
            #pragma unroll
            for (int ni = 0; ni < 8; ++ni)
                #pragma unroll
                for (int r = 0; r < 4; ++r) acc[mi][ni][r] = 0.f;
        for (int chunk = 0; chunk < 4; ++chunk, ++s) {
            CP_WAIT0();
            __syncthreads();
            if (s + 1 < NSTEPS) { fill_B(sB, s + 1); CP_COMMIT(); }
            chunk_mma(sA + chunk * A_CHUNK_BYTES,
                      sB + (s & 1) * B_CHUNK_BYTES, lane, acc, wm, wn);
        }

        // ---- Phase 1: scores in place, register min, shared atomicMin ----
        #pragma unroll
        for (int ni = 0; ni < 8; ++ni) {
            int c0 = tile * BN + wn + ni * 8 + ((lane & 3) << 1);
            float e0 = __ldg(&g_enorm[c0]);
            float e1 = __ldg(&g_enorm[c0 + 1]);
            #pragma unroll
            for (int mi = 0; mi < 4; ++mi) {
                acc[mi][ni][0] = e0 - acc[mi][ni][0];
                acc[mi][ni][1] = e1 - acc[mi][ni][1];
                acc[mi][ni][2] = e0 - acc[mi][ni][2];
                acc[mi][ni][3] = e1 - acc[mi][ni][3];
            }
        }
        #pragma unroll
        for (int mi = 0; mi < 4; ++mi) {
            #pragma unroll
            for (int h = 0; h < 2; ++h) {
                float vmin = fminf(acc[mi][0][2*h], acc[mi][0][2*h+1]);
                #pragma unroll
                for (int ni = 1; ni < 8; ++ni)
                    vmin = fminf(vmin, fminf(acc[mi][ni][2*h], acc[mi][ni][2*h+1]));
                int rloc = wm + mi * 16 + (lane >> 2) + h * 8;
                atomicMin(&rowminS[rloc], fmap(vmin));
            }
        }
        __syncthreads();

        // ---- Phase 2: branch-free masks; one cold branch per slice ----
        #pragma unroll
        for (int mi = 0; mi < 4; ++mi) {
            #pragma unroll
            for (int h = 0; h < 2; ++h) {
                int rloc = wm + mi * 16 + (lane >> 2) + h * 8;
                float thr = funmap(rowminS[rloc]) + MARGIN;
                uint32_t mask = 0;
                #pragma unroll
                for (int ni = 0; ni < 8; ++ni) {
                    mask |= (acc[mi][ni][2*h]   < thr) ? (1u << (2*ni))     : 0u;
                    mask |= (acc[mi][ni][2*h+1] < thr) ? (1u << (2*ni + 1)) : 0u;
                }
                if (mask) {
                    int cb = tile * BN + wn + ((lane & 3) << 1);
                    do {
                        int b = __ffs(mask) - 1;
                        mask &= mask - 1;
                        int code = cb + (b >> 1) * 8 + (b & 1);
                        int qi = atomicAdd(qcount, 1);
                        if (qi < QSLAB) myq[qi] = ((uint32_t)rloc << 11) | (uint32_t)code;
                        else *qovf = 1;
                    } while (mask);
                }
            }
        }
    }

    // ======================= Exact fp32 rescore ============================
    __syncthreads();
    int qn = *qcount; if (qn > QSLAB) qn = QSLAB;
    for (int q = tid; q < qn; q += 128) {
        uint32_t ent = myq[q];
        exact_rescore(z, e, row0, (int)(ent >> 11), (int)(ent & 2047u), rowbest);
    }
    // Cold fallback: queue overflowed (never in practice) -> brute force.
    if (*qovf) {
        for (int code = 0; code < KCODES; ++code)
            exact_rescore(z, e, row0, tid, code, rowbest);
    }
    __syncthreads();

    // ---- Indices + histogram; publish bi for the fused gather ----
    {
        int bi = (int)(rowbest[tid] & 0xFFFFFFFFull);
        int row = row0 + tid;
        out[(size_t)NROWS * DIM + 1 + row] = (float)bi;    // encoding index
        atomicAdd(&g_counts[bi], 1.0f);
        rowminS[tid] = (uint32_t)bi;                       // reuse as idx array
    }
    __syncthreads();

    // ---- Fused gather z_q + commitment-loss partial ----
    {
        const float4* eb = (const float4*)e;
        const float4* zb = (const float4*)(z + (size_t)row0 * DIM);
        float4* ob = (float4*)(out + (size_t)row0 * DIM);
        float ls = 0.f;
        #pragma unroll 4
        for (int u = tid; u < BM * 64; u += 128) {
            int row = u >> 6, c4 = u & 63;
            int bi = (int)rowminS[row];
            float4 ev = __ldg(&eb[(size_t)bi * 64 + c4]);
            float4 zv = zb[u];
            ob[u] = ev;
            float dx = ev.x - zv.x, dy = ev.y - zv.y;
            float dz = ev.z - zv.z, dw = ev.w - zv.w;
            ls += dx * dx + dy * dy + dz * dz + dw * dw;
        }
        #pragma unroll
        for (int o = 16; o; o >>= 1) ls += __shfl_xor_sync(0xffffffffu, ls, o);
        __shared__ float red[4];
        if (lane == 0) red[w] = ls;
        __syncthreads();
        if (tid == 0)
            atomicAdd(&g_loss_sum, red[0] + red[1] + red[2] + red[3]);
    }
}

// ---------------------------------------------------------------------------
// Finalize: loss scalar + perplexity.
// ---------------------------------------------------------------------------
__global__ void finalize_kernel(float* __restrict__ out) {
    const float invN = 1.0f / (float)NROWS;
    float s = 0.f;
    for (int k = threadIdx.x; k < KCODES; k += blockDim.x) {
        float p = g_counts[k] * invN;
        s += p * logf(p + 1e-10f);
    }
    __shared__ float red[32];
    #pragma unroll
    for (int o = 16; o; o >>= 1) s += __shfl_xor_sync(0xffffffffu, s, o);
    int l = threadIdx.x & 31, wq = threadIdx.x >> 5;
    if (l == 0) red[wq] = s;
    __syncthreads();
    if (wq == 0) {
        float v = (l < ((int)blockDim.x >> 5)) ? red[l] : 0.f;
        #pragma unroll
        for (int o = 16; o; o >>= 1) v += __shfl_xor_sync(0xffffffffu, v, o);
        if (l == 0) {
            const size_t NZ = (size_t)NROWS * DIM;
            out[NZ] = 0.25f * g_loss_sum / (float)NZ;
            out[NZ + 1 + NROWS] = expf(-v);
        }
    }
}

// ---------------------------------------------------------------------------
// Output layout (flattened tuple, float32):
//   [0, N*D) z_q_st | [N*D] loss | [N*D+1, +N) indices | [N*D+1+N] perplexity
// ---------------------------------------------------------------------------
extern "C" void kernel_launch(void* const* d_in, const int* in_sizes, int n_in,
                              void* d_out, int out_size) {
    const float* z = (const float*)d_in[0];
    const float* e = (const float*)d_in[1];
    float* out = (float*)d_out;

    cudaFuncSetAttribute(argmin_mma_kernel,
                         cudaFuncAttributeMaxDynamicSharedMemorySize, SMEM_BYTES);

    prep_z_kernel<<<(NROWS * 64) / 256, 256>>>(z);
    prep_e_kernel<<<KCODES * 32 / 256, 256>>>(e);
    argmin_mma_kernel<<<NROWS / BM, 128, SMEM_BYTES>>>(z, e, out);
    finalize_kernel<<<1, 256>>>(out);
}

// round 16
// speedup vs baseline: 2.1157x; 1.0721x over previous
#include <cuda_runtime.h>
#include <cuda_bf16.h>
#include <math.h>
#include <cstdint>

// ---------------------------------------------------------------------------
// Problem constants
// ---------------------------------------------------------------------------
#define DIM     256
#define KCODES  2048
#define NROWS   65536
#define BM      128            // z rows per rowblock
#define BN      128            // codes per tile
#define NRBLK   512            // NROWS / BM
#define NUNITS  2048           // 512 rowblocks * 4 quarters
#define NCTAS   304            // persistent CTAs (2 per SM, up to 152 SMs)

#define MARGIN  1.5f           // > 2x max plausible hh-score error (~0.7)
#define QSLAB   4096           // queue entries per CTA slab (per unit)

#define A_CHUNK_BYTES 16384    // 128 rows * 64 k * 2B
#define A_BYTES       65536    // 4 chunks
#define B_CHUNK_BYTES 16384
// smem: [0,64K) A | [64K,96K) B db | rowminS[128] | qcount | qovf | s_unit
#define OFF_ROWMIN  98304
#define OFF_QCOUNT  98816
#define OFF_QOVF    98820
#define OFF_UNIT    98824
#define SMEM_BYTES  100352

// ---------------------------------------------------------------------------
// Device scratch (static)
// ---------------------------------------------------------------------------
__device__ float g_enorm[KCODES];
__device__ float g_counts[KCODES];
__device__ float g_loss_sum;
__device__ int   g_ucounter;
__device__ uint32_t g_rowmin[NROWS];                       // order-mapped float
__device__ unsigned long long g_rowbest[NROWS];            // (score|code) key
__device__ __align__(16) __nv_bfloat16 g_es[KCODES * DIM];            // 1 MB
__device__ __align__(16) __nv_bfloat16 g_zs[(size_t)NROWS * DIM];     // 32 MB
__device__ uint32_t g_queue[(size_t)NCTAS * QSLAB];

// ---------------------------------------------------------------------------
// PTX helpers
// ---------------------------------------------------------------------------
__device__ __forceinline__ uint32_t smem_u32(const void* p) {
    uint32_t a;
    asm("{ .reg .u64 t; cvta.to.shared.u64 t, %1; cvt.u32.u64 %0, t; }"
        : "=r"(a) : "l"(p));
    return a;
}
__device__ __forceinline__ void cp16(uint32_t dst, const void* src) {
    asm volatile("cp.async.cg.shared.global [%0], [%1], 16;" :: "r"(dst), "l"(src));
}
#define CP_COMMIT() asm volatile("cp.async.commit_group;" ::: "memory")
#define CP_WAIT0()  asm volatile("cp.async.wait_group 0;" ::: "memory")

#define LDSM_X4(r, addr) \
    asm volatile("ldmatrix.sync.aligned.m8n8.x4.shared.b16 {%0,%1,%2,%3}, [%4];" \
        : "=r"((r)[0]), "=r"((r)[1]), "=r"((r)[2]), "=r"((r)[3]) : "r"(addr))

#define LDSM_X4B(r0, r1, r2, r3, addr) \
    asm volatile("ldmatrix.sync.aligned.m8n8.x4.shared.b16 {%0,%1,%2,%3}, [%4];" \
        : "=r"(r0), "=r"(r1), "=r"(r2), "=r"(r3) : "r"(addr))

#define MMA16816(d, a, b) \
    asm volatile("mma.sync.aligned.m16n8k16.row.col.f32.bf16.bf16.f32 " \
        "{%0,%1,%2,%3}, {%4,%5,%6,%7}, {%8,%9}, {%0,%1,%2,%3};" \
        : "+f"((d)[0]), "+f"((d)[1]), "+f"((d)[2]), "+f"((d)[3]) \
        : "r"((a)[0]), "r"((a)[1]), "r"((a)[2]), "r"((a)[3]), \
          "r"((b)[0]), "r"((b)[1]))

__device__ __forceinline__ uint32_t pack2h(float a, float b) {
    __nv_bfloat16 h0 = __float2bfloat16(a), h1 = __float2bfloat16(b);
    return ((uint32_t)__bfloat16_as_ushort(h1) << 16) |
           (uint32_t)__bfloat16_as_ushort(h0);
}

// Order-preserving float <-> uint maps.
__device__ __forceinline__ uint32_t fmap(float f) {
    uint32_t s = __float_as_uint(f);
    return (s & 0x80000000u) ? ~s : (s | 0x80000000u);
}
__device__ __forceinline__ float funmap(uint32_t u) {
    return (u & 0x80000000u) ? __uint_as_float(u & 0x7FFFFFFFu)
                             : __uint_as_float(~u);
}

// ---------------------------------------------------------------------------
// Prep 1: z -> g_zs (bf16 hi); init per-row global state.
// ---------------------------------------------------------------------------
__global__ void prep_z_kernel(const float* __restrict__ z) {
    int i = blockIdx.x * blockDim.x + threadIdx.x;
    float4 v = ((const float4*)z)[i];
    ((uint2*)g_zs)[i] = make_uint2(pack2h(v.x, v.y), pack2h(v.z, v.w));
    if (i < NROWS) {
        g_rowmin[i] = fmap(3.0e38f);
        g_rowbest[i] = ~0ull;
    }
}

// ---------------------------------------------------------------------------
// Prep 2: e -> g_es (bf16 hi) + half-norms + zero scratch. One warp per code.
// ---------------------------------------------------------------------------
__global__ void prep_e_kernel(const float* __restrict__ e) {
    int t = blockIdx.x * blockDim.x + threadIdx.x;
    int w = t >> 5, l = t & 31;
    if (w < KCODES) {
        const float4* row = (const float4*)(e + (size_t)w * DIM);
        float4 a = row[2 * l], b = row[2 * l + 1];
        uint32_t ph[4] = {pack2h(a.x, a.y), pack2h(a.z, a.w),
                          pack2h(b.x, b.y), pack2h(b.z, b.w)};
        ((uint4*)g_es)[(size_t)w * 32 + l] = *(uint4*)ph;
        float s = a.x*a.x + a.y*a.y + a.z*a.z + a.w*a.w
                + b.x*b.x + b.y*b.y + b.z*b.z + b.w*b.w;
        #pragma unroll
        for (int o = 16; o; o >>= 1) s += __shfl_xor_sync(0xffffffffu, s, o);
        if (l == 0) { g_enorm[w] = 0.5f * s; g_counts[w] = 0.f; }
    }
    if (t == 0) { g_loss_sum = 0.f; g_ucounter = 0; }
}

// ---------------------------------------------------------------------------
// B chunk fill: 128 codes x 64 k of eh into swizzled smem buffer `buf`.
// ---------------------------------------------------------------------------
__device__ __forceinline__ void fill_B(uint32_t sB, int tile, int chunk, int buf) {
    const char* src0 = (const char*)g_es + (size_t)tile * BN * 512 + chunk * 128;
    uint32_t d0 = sB + buf * B_CHUNK_BYTES;
    #pragma unroll
    for (int o = 0; o < 8; ++o) {
        int idx = threadIdx.x + o * 128;
        int row = idx >> 3, seg = idx & 7;
        uint32_t dst = d0 + row * 128 + (((uint32_t)(seg ^ (row & 7))) << 4);
        cp16(dst, src0 + (size_t)row * 512 + seg * 16);
    }
}

// ---------------------------------------------------------------------------
// One hh chunk: 4 ks-steps of (8 LDSM.x4 + 32 MMA). Maps proven R5/R6/R10.
// ---------------------------------------------------------------------------
__device__ __forceinline__ void chunk_mma(
    uint32_t aBase, uint32_t bBase, int lane,
    float (&acc)[4][8][4], int wm, int wn)
{
    const int m = lane >> 3, r8 = lane & 7;
    #pragma unroll
    for (int ks = 0; ks < 4; ++ks) {
        uint32_t b[8][2];
        #pragma unroll
        for (int nb = 0; nb < 4; ++nb) {
            int code = wn + nb * 16 + ((m >> 1) << 3) + r8;
            int kseg = ks * 2 + (m & 1);
            uint32_t addr = bBase + code * 128 +
                            (((uint32_t)(kseg ^ (code & 7))) << 4);
            LDSM_X4B(b[2 * nb][0], b[2 * nb][1],
                     b[2 * nb + 1][0], b[2 * nb + 1][1], addr);
        }
        uint32_t a[4][4];
        #pragma unroll
        for (int mi = 0; mi < 4; ++mi) {
            int row = wm + mi * 16 + r8 + ((m & 1) << 3);
            int kseg = ks * 2 + (m >> 1);
            uint32_t addr = aBase + row * 128 +
                            (((uint32_t)(kseg ^ (row & 7))) << 4);
            LDSM_X4(a[mi], addr);
        }
        #pragma unroll
        for (int mi = 0; mi < 4; ++mi)
            #pragma unroll
            for (int ni = 0; ni < 8; ++ni)
                MMA16816(acc[mi][ni], a[mi], b[ni]);
    }
}

// ---------------------------------------------------------------------------
// Exact fp32 rescore -> global rowbest. Post-tile-loop only.
// ---------------------------------------------------------------------------
__device__ __forceinline__ void exact_rescore(
    const float* __restrict__ z, const float* __restrict__ e,
    int grow, int code)
{
    const float4* zr = (const float4*)(z + (size_t)grow * DIM);
    const float4* er = (const float4*)(e + (size_t)code * DIM);
    float a0 = 0.f, a1 = 0.f, a2 = 0.f, a3 = 0.f;
    #pragma unroll 8
    for (int i = 0; i < 64; ++i) {
        float4 zv = __ldg(&zr[i]);
        float4 ev = __ldg(&er[i]);
        a0 += zv.x * ev.x; a1 += zv.y * ev.y;
        a2 += zv.z * ev.z; a3 += zv.w * ev.w;
    }
    float sc = __ldg(&g_enorm[code]) - ((a0 + a1) + (a2 + a3));
    unsigned long long key = ((unsigned long long)fmap(sc) << 32) | (uint32_t)code;
    atomicMin(&g_rowbest[grow], key);
}

// ---------------------------------------------------------------------------
// Main kernel: persistent CTAs; unit = (rowblock, code quarter). hh GEMM +
// margin gating against global row minima; per-unit exact rescore.
// ---------------------------------------------------------------------------
__global__ void __launch_bounds__(128, 2)
argmin_mma_kernel(const float* __restrict__ z, const float* __restrict__ e) {
    extern __shared__ char smem[];
    const int tid = threadIdx.x, lane = tid & 31, w = tid >> 5;
    const int wm = (w >> 1) * 64, wn = (w & 1) * 64;
    const uint32_t sA = smem_u32(smem);
    const uint32_t sB = sA + A_BYTES;
    uint32_t* rowminS = (uint32_t*)(smem + OFF_ROWMIN);
    int* qcount = (int*)(smem + OFF_QCOUNT);
    int* qovf   = (int*)(smem + OFF_QOVF);
    int* s_unit = (int*)(smem + OFF_UNIT);
    uint32_t* myq = g_queue + (size_t)blockIdx.x * QSLAB;

    if (tid == 0) { *qcount = 0; *qovf = 0; }

    for (;;) {
        if (tid == 0) *s_unit = atomicAdd(&g_ucounter, 1);
        __syncthreads();
        int u = *s_unit;
        if (u >= NUNITS) break;
        // quarter-major order: all quarter-0 units first (warm thresholds).
        int rowblock = u & (NRBLK - 1);
        int qt = u >> 9;
        int row0 = rowblock * BM;
        rowminS[tid] = fmap(3.0e38f);

        // ---- Unit prologue: A (4 chunks) + first B chunk, one group ----
        {
            const char* gA = (const char*)g_zs + (size_t)row0 * 512;
            for (int o = tid; o < 4096; o += 128) {
                int chunk = o >> 10, rem = o & 1023;
                int row = rem >> 3, seg = rem & 7;
                uint32_t dst = sA + chunk * A_CHUNK_BYTES + row * 128 +
                               (((uint32_t)(seg ^ (row & 7))) << 4);
                cp16(dst, gA + (size_t)row * 512 + chunk * 128 + seg * 16);
            }
            fill_B(sB, qt * 4, 0, 0);
            CP_COMMIT();
        }

        int ls = 0;
        for (int t = 0; t < 4; ++t) {
            int tile = qt * 4 + t;
            float acc[4][8][4];
            #pragma unroll
            for (int mi = 0; mi < 4; ++mi)
                #pragma unroll
                for (int ni = 0; ni < 8; ++ni)
                    #pragma unroll
                    for (int r = 0; r < 4; ++r) acc[mi][ni][r] = 0.f;
            for (int chunk = 0; chunk < 4; ++chunk, ++ls) {
                CP_WAIT0();
                __syncthreads();
                if (ls + 1 < 16) {
                    fill_B(sB, qt * 4 + ((ls + 1) >> 2), (ls + 1) & 3, (ls + 1) & 1);
                    CP_COMMIT();
                }
                chunk_mma(sA + chunk * A_CHUNK_BYTES,
                          sB + (ls & 1) * B_CHUNK_BYTES, lane, acc, wm, wn);
            }

            // ---- Scores in place ----
            #pragma unroll
            for (int ni = 0; ni < 8; ++ni) {
                int c0 = tile * BN + wn + ni * 8 + ((lane & 3) << 1);
                float e0 = __ldg(&g_enorm[c0]);
                float e1 = __ldg(&g_enorm[c0 + 1]);
                #pragma unroll
                for (int mi = 0; mi < 4; ++mi) {
                    acc[mi][ni][0] = e0 - acc[mi][ni][0];
                    acc[mi][ni][1] = e1 - acc[mi][ni][1];
                    acc[mi][ni][2] = e0 - acc[mi][ni][2];
                    acc[mi][ni][3] = e1 - acc[mi][ni][3];
                }
            }

            // ---- Per-slice mins ----
            float vmin8[8];
            {
                int k = 0;
                #pragma unroll
                for (int mi = 0; mi < 4; ++mi)
                    #pragma unroll
                    for (int h = 0; h < 2; ++h, ++k) {
                        float vm = fminf(acc[mi][0][2*h], acc[mi][0][2*h+1]);
                        #pragma unroll
                        for (int ni = 1; ni < 8; ++ni)
                            vm = fminf(vm, fminf(acc[mi][ni][2*h], acc[mi][ni][2*h+1]));
                        vmin8[k] = vm;
                    }
            }

            uint32_t thrm8[8];   // mapped-space known-min per slice
            if (t == 0) {
                // two-phase seed: smem min -> merge global -> gate
                int k = 0;
                #pragma unroll
                for (int mi = 0; mi < 4; ++mi)
                    #pragma unroll
                    for (int h = 0; h < 2; ++h, ++k) {
                        int rloc = wm + mi * 16 + (lane >> 2) + h * 8;
                        atomicMin(&rowminS[rloc], fmap(vmin8[k]));
                    }
                __syncthreads();
                if (tid < BM) {
                    uint32_t sm = rowminS[tid];
                    uint32_t old = atomicMin(&g_rowmin[row0 + tid], sm);
                    rowminS[tid] = (old < sm) ? old : sm;
                }
                __syncthreads();
                k = 0;
                #pragma unroll
                for (int mi = 0; mi < 4; ++mi)
                    #pragma unroll
                    for (int h = 0; h < 2; ++h, ++k)
                        thrm8[k] = rowminS[wm + mi * 16 + (lane >> 2) + h * 8];
            } else {
                // sync-free: publish + use returned old
                int k = 0;
                #pragma unroll
                for (int mi = 0; mi < 4; ++mi)
                    #pragma unroll
                    for (int h = 0; h < 2; ++h, ++k) {
                        int rloc = wm + mi * 16 + (lane >> 2) + h * 8;
                        uint32_t vm = fmap(vmin8[k]);
                        uint32_t old = atomicMin(&g_rowmin[row0 + rloc], vm);
                        thrm8[k] = (old < vm) ? old : vm;
                    }
            }

            // ---- Gate + enqueue (branch-free masks, one cold branch/slice) --
            {
                int k = 0;
                #pragma unroll
                for (int mi = 0; mi < 4; ++mi)
                    #pragma unroll
                    for (int h = 0; h < 2; ++h, ++k) {
                        int rloc = wm + mi * 16 + (lane >> 2) + h * 8;
                        float thr = funmap(thrm8[k]) + MARGIN;
                        uint32_t mask = 0;
                        #pragma unroll
                        for (int ni = 0; ni < 8; ++ni) {
                            mask |= (acc[mi][ni][2*h]   < thr) ? (1u << (2*ni))   : 0u;
                            mask |= (acc[mi][ni][2*h+1] < thr) ? (1u << (2*ni+1)) : 0u;
                        }
                        if (mask) {
                            int cb = tile * BN + wn + ((lane & 3) << 1);
                            do {
                                int b = __ffs(mask) - 1;
                                mask &= mask - 1;
                                int code = cb + (b >> 1) * 8 + (b & 1);
                                int qi = atomicAdd(qcount, 1);
                                if (qi < QSLAB)
                                    myq[qi] = ((uint32_t)rloc << 11) | (uint32_t)code;
                                else *qovf = 1;
                            } while (mask);
                        }
                    }
            }
        }

        // ---- Unit-end exact rescore ----
        __syncthreads();
        int qn = *qcount; if (qn > QSLAB) qn = QSLAB;
        for (int q = tid; q < qn; q += 128) {
            uint32_t ent = myq[q];
            exact_rescore(z, e, row0 + (int)(ent >> 11), (int)(ent & 2047u));
        }
        if (*qovf) {   // cold: brute-force this unit's quarter
            for (int c = 0; c < 512; ++c)
                exact_rescore(z, e, row0 + tid, qt * 512 + c);
        }
        __syncthreads();
        if (tid == 0) { *qcount = 0; *qovf = 0; }
    }
}

// ---------------------------------------------------------------------------
// Gather z_q + commitment loss + index output + histogram.
// ---------------------------------------------------------------------------
__global__ void gather_loss_kernel(const float* __restrict__ z,
                                   const float* __restrict__ e,
                                   float* __restrict__ out) {
    int i = blockIdx.x * blockDim.x + threadIdx.x;
    int row = i >> 6;
    int c4 = i & 63;
    int idx = (int)(g_rowbest[row] & 0xFFFFFFFFull);
    if (c4 == 0) {
        out[(size_t)NROWS * DIM + 1 + row] = (float)idx;
        atomicAdd(&g_counts[idx], 1.0f);
    }
    float4 ev = ((const float4*)e)[(size_t)idx * 64 + c4];
    float4 zv = ((const float4*)z)[i];
    ((float4*)out)[i] = ev;
    float dx = ev.x - zv.x, dy = ev.y - zv.y;
    float dz = ev.z - zv.z, dw = ev.w - zv.w;
    float ls = dx * dx + dy * dy + dz * dz + dw * dw;

    __shared__ float red[32];
    #pragma unroll
    for (int o = 16; o; o >>= 1) ls += __shfl_xor_sync(0xffffffffu, ls, o);
    int l = threadIdx.x & 31, wq = threadIdx.x >> 5;
    if (l == 0) red[wq] = ls;
    __syncthreads();
    if (wq == 0) {
        float v = (l < ((int)blockDim.x >> 5)) ? red[l] : 0.f;
        #pragma unroll
        for (int o = 16; o; o >>= 1) v += __shfl_xor_sync(0xffffffffu, v, o);
        if (l == 0) atomicAdd(&g_loss_sum, v);
    }
}

// ---------------------------------------------------------------------------
// Finalize: loss scalar + perplexity.
// ---------------------------------------------------------------------------
__global__ void finalize_kernel(float* __restrict__ out) {
    const float invN = 1.0f / (float)NROWS;
    float s = 0.f;
    for (int k = threadIdx.x; k < KCODES; k += blockDim.x) {
        float p = g_counts[k] * invN;
        s += p * logf(p + 1e-10f);
    }
    __shared__ float red[32];
    #pragma unroll
    for (int o = 16; o; o >>= 1) s += __shfl_xor_sync(0xffffffffu, s, o);
    int l = threadIdx.x & 31, wq = threadIdx.x >> 5;
    if (l == 0) red[wq] = s;
    __syncthreads();
    if (wq == 0) {
        float v = (l < ((int)blockDim.x >> 5)) ? red[l] : 0.f;
        #pragma unroll
        for (int o = 16; o; o >>= 1) v += __shfl_xor_sync(0xffffffffu, v, o);
        if (l == 0) {
            const size_t NZ = (size_t)NROWS * DIM;
            out[NZ] = 0.25f * g_loss_sum / (float)NZ;
            out[NZ + 1 + NROWS] = expf(-v);
        }
    }
}

// ---------------------------------------------------------------------------
// Output layout (flattened tuple, float32):
//   [0, N*D) z_q_st | [N*D] loss | [N*D+1, +N) indices | [N*D+1+N] perplexity
// ---------------------------------------------------------------------------
extern "C" void kernel_launch(void* const* d_in, const int* in_sizes, int n_in,
                              void* d_out, int out_size) {
    const float* z = (const float*)d_in[0];
    const float* e = (const float*)d_in[1];
    float* out = (float*)d_out;

    cudaFuncSetAttribute(argmin_mma_kernel,
                         cudaFuncAttributeMaxDynamicSharedMemorySize, SMEM_BYTES);

    prep_z_kernel<<<(NROWS * 64) / 256, 256>>>(z);
    prep_e_kernel<<<KCODES * 32 / 256, 256>>>(e);
    argmin_mma_kernel<<<NCTAS, 128, SMEM_BYTES>>>(z, e);
    gather_loss_kernel<<<(NROWS * (DIM / 4)) / 256, 256>>>(z, e, out);
    finalize_kernel<<<1, 256>>>(out);
}